// round 15
// baseline (speedup 1.0000x reference)
#include <cuda_runtime.h>
#include <cuda_fp16.h>
#include <math.h>

typedef unsigned int u32;
typedef unsigned long long u64;

// Problem constants
constexpr int B_    = 8192;
constexpr int NE_   = 20000;
constexpr int H_    = 512;
constexpr int C_    = 50;
constexpr int KIN_  = 25600;          // C_*H_
constexpr int NPAN  = 157;            // ceil(20000/128) score n-panels
constexpr int NSPL  = 8;              // FC split-K factor
constexpr float SHIFT = 50.f;         // fixed softmax shift (scores |v| <~ 100)

// ---------------- scratch (static device memory; no allocations) -------------
__device__ float g_xs[(size_t)B_ * 3 * H_];
__device__ float g_part0[B_ * 6];
__device__ float g_s0[3], g_t0[3];
__device__ float g_part1[(size_t)B_ * 66];     // per-block Vraw(9)+Mraw(45)+edges(12)
__device__ double g_v66[66];
__device__ float g_s1[C_], g_t1[C_];
__device__ __half g_a16[(size_t)B_ * KIN_];    // A fp16 (420 MB)
__device__ __half g_w16[(size_t)H_ * KIN_];    // fc_w fp16
__device__ __half g_e16[(size_t)NE_ * H_];     // ent fp16
__device__ __half g_z16[(size_t)B_ * H_];      // z fp16
__device__ float g_fcs[(size_t)NSPL * B_ * H_];// FC split-K partials (128 MB)
__device__ float g_fc[B_ * H_];
__device__ float g_part2[256 * 1024];
__device__ float g_s2[H_], g_t2[H_];
__device__ float g_ps[(size_t)B_ * NPAN];      // per-panel row sumexp(v-SHIFT)
__device__ float g_lse[B_];

// ---------------- PTX helpers (portable: sm_80+ instructions only) -----------
static __device__ __forceinline__ u32 smem_u32(const void* p) {
    u32 a;
    asm("{ .reg .u64 t; cvta.to.shared.u64 t, %1; cvt.u32.u64 %0, t; }" : "=r"(a) : "l"(p));
    return a;
}

#define CP_ASYNC16(saddr, gptr, srcsz) \
    asm volatile("cp.async.cg.shared.global [%0], [%1], 16, %2;" \
                 :: "r"(saddr), "l"(gptr), "r"(srcsz) : "memory")
#define CP_COMMIT() asm volatile("cp.async.commit_group;" ::: "memory")

#define LDM_X4(r0, r1, r2, r3, addr) \
    asm volatile("ldmatrix.sync.aligned.m8n8.x4.shared.b16 {%0,%1,%2,%3}, [%4];" \
                 : "=r"(r0), "=r"(r1), "=r"(r2), "=r"(r3) : "r"(addr))

#define MMA16816(d, a, b0, b1) \
    asm volatile("mma.sync.aligned.m16n8k16.row.col.f32.f16.f16.f32 " \
                 "{%0,%1,%2,%3},{%4,%5,%6,%7},{%8,%9},{%0,%1,%2,%3};" \
                 : "+f"((d)[0]), "+f"((d)[1]), "+f"((d)[2]), "+f"((d)[3]) \
                 : "r"((a)[0]), "r"((a)[1]), "r"((a)[2]), "r"((a)[3]), \
                   "r"(b0), "r"(b1))

// ======================= K1: gather + bn0 sums + raw conv moments =============
__global__ void k_gather(const int* __restrict__ facts, const float* __restrict__ ent,
                         const float* __restrict__ rel, const float* __restrict__ erb)
{
    __shared__ float xn[3][514];        // raw values, zero-padded
    __shared__ float redm[4][54];
    __shared__ float red0[4][6];
    int b = blockIdx.x, t = threadIdx.x;   // 128 threads
    int f0 = facts[b * 3 + 0];
    int f1 = facts[b * 3 + 1];
    const float* r0 = ent + (size_t)f0 * H_;
    const float* r1 = rel + (size_t)f1 * H_;
    const float* r2 = erb + (size_t)f0 * H_;
    float* xb = g_xs + (size_t)b * 3 * H_;

    float s[3] = {0.f, 0.f, 0.f}, q[3] = {0.f, 0.f, 0.f};
    for (int h = t; h < H_; h += 128) {
        float v0 = r0[h], v1 = r1[h], v2 = r2[h];
        xb[h] = v0; xb[H_ + h] = v1; xb[2 * H_ + h] = v2;
        xn[0][h + 1] = v0; xn[1][h + 1] = v1; xn[2][h + 1] = v2;
        s[0] += v0; q[0] += v0 * v0;
        s[1] += v1; q[1] += v1 * v1;
        s[2] += v2; q[2] += v2 * v2;
    }
    if (t < 3) { xn[t][0] = 0.f; xn[t][513] = 0.f; }
    __syncthreads();

    float acc[54];
    #pragma unroll
    for (int i = 0; i < 54; i++) acc[i] = 0.f;
    #pragma unroll
    for (int jj = 0; jj < 4; jj++) {
        int h = t + jj * 128;
        float u[9];
        #pragma unroll
        for (int i = 0; i < 3; i++)
            #pragma unroll
            for (int k = 0; k < 3; k++)
                u[i * 3 + k] = xn[i][h + k];
        #pragma unroll
        for (int i = 0; i < 9; i++) acc[i] += u[i];
        int idx = 9;
        #pragma unroll
        for (int i = 0; i < 9; i++)
            #pragma unroll
            for (int j = 0; j <= i; j++)
                acc[idx++] += u[i] * u[j];
    }

    #pragma unroll
    for (int i = 0; i < 3; i++) {
        #pragma unroll
        for (int o = 16; o; o >>= 1) {
            s[i] += __shfl_xor_sync(0xffffffffu, s[i], o);
            q[i] += __shfl_xor_sync(0xffffffffu, q[i], o);
        }
    }
    #pragma unroll
    for (int i = 0; i < 54; i++) {
        #pragma unroll
        for (int o = 16; o; o >>= 1)
            acc[i] += __shfl_xor_sync(0xffffffffu, acc[i], o);
    }
    int w = t >> 5, ln = t & 31;
    if (ln == 0) {
        #pragma unroll
        for (int i = 0; i < 3; i++) { red0[w][i] = s[i]; red0[w][3 + i] = q[i]; }
        #pragma unroll
        for (int i = 0; i < 54; i++) redm[w][i] = acc[i];
    }
    __syncthreads();
    if (t < 6)
        g_part0[b * 6 + t] = red0[0][t] + red0[1][t] + red0[2][t] + red0[3][t];
    if (t < 54)
        g_part1[(size_t)b * 66 + t] = redm[0][t] + redm[1][t] + redm[2][t] + redm[3][t];
    else if (t < 66) {
        int e = t - 54, c = e >> 2, p = e & 3;
        int pos = (p == 0) ? 0 : (p == 1) ? 1 : (p == 2) ? 510 : 511;
        g_part1[(size_t)b * 66 + t] = xn[c][pos + 1];
    }
}

// ======================= K2: finalize bn0 (grid=3) ============================
__global__ void k_fin0(const float* __restrict__ gg, const float* __restrict__ bb)
{
    int c = blockIdx.x, t = threadIdx.x;
    __shared__ double sd[256], sq[256];
    double s = 0.0, q = 0.0;
    for (int j = t; j < B_; j += 256) {
        s += (double)g_part0[j * 6 + c];
        q += (double)g_part0[j * 6 + 3 + c];
    }
    sd[t] = s; sq[t] = q; __syncthreads();
    for (int o = 128; o; o >>= 1) {
        if (t < o) { sd[t] += sd[t + o]; sq[t] += sq[t + o]; }
        __syncthreads();
    }
    if (t == 0) {
        double cnt  = (double)B_ * (double)H_;
        double mean = sd[0] / cnt;
        double var  = sq[0] / cnt - mean * mean;
        double sc   = (double)gg[c] / sqrt(var + 1e-5);
        g_s0[c] = (float)sc;
        g_t0[c] = (float)((double)bb[c] - mean * sc);
    }
}

// ======================= K4a: reduce 66 raw components over blocks ============
__global__ void k_fin1a()
{
    int comp = blockIdx.x, t = threadIdx.x;
    __shared__ double sd[256];
    double s = 0.0;
    for (int j = t; j < B_; j += 256) s += (double)g_part1[(size_t)j * 66 + comp];
    sd[t] = s; __syncthreads();
    for (int o = 128; o; o >>= 1) { if (t < o) sd[t] += sd[t + o]; __syncthreads(); }
    if (t == 0) g_v66[comp] = sd[0];
}

// ======================= K4b: bn1 params via affine-corrected moments =========
__global__ void k_fin1b(const float* __restrict__ cw, const float* __restrict__ cb,
                        const float* __restrict__ gg, const float* __restrict__ bb)
{
    int c = threadIdx.x;
    if (c >= C_) return;

    double a[3], bo[3];
    #pragma unroll
    for (int ch = 0; ch < 3; ch++) { a[ch] = (double)g_s0[ch]; bo[ch] = (double)g_t0[ch]; }
    double Vr[9];
    #pragma unroll
    for (int i = 0; i < 9; i++) Vr[i] = g_v66[i];
    double e0v[9], e5v[9];
    #pragma unroll
    for (int i = 0; i < 9; i++) {
        int ki = i % 3, ci = i / 3;
        e0v[i] = (ki == 1) ? g_v66[54 + ci * 4 + 0] : (ki == 2) ? g_v66[54 + ci * 4 + 1] : 0.0;
        e5v[i] = (ki == 0) ? g_v66[54 + ci * 4 + 2] : (ki == 1) ? g_v66[54 + ci * 4 + 3] : 0.0;
    }

    double w[9];
    #pragma unroll
    for (int i = 0; i < 9; i++) w[i] = (double)cw[c * 9 + i];
    double cbv = (double)cb[c];
    double Bf = (double)B_;
    double N = Bf * 512.0;

    double dot = 0.0;
    #pragma unroll
    for (int i = 0; i < 9; i++) {
        int ki = i % 3;
        double ni = 512.0 - (ki == 0 ? 1.0 : 0.0) - (ki == 2 ? 1.0 : 0.0);
        double Vp = a[i / 3] * Vr[i] + bo[i / 3] * Bf * ni;
        dot += w[i] * Vp;
    }
    double sy = cbv * N + dot;
    double sq = cbv * cbv * N + 2.0 * cbv * dot;

    #pragma unroll
    for (int i = 0; i < 9; i++) {
        #pragma unroll
        for (int j = 0; j <= i; j++) {
            int ki = i % 3, kj = j % 3;
            double Mr = g_v66[9 + i * (i + 1) / 2 + j];
            double nij = 512.0 - ((ki == 0 || kj == 0) ? 1.0 : 0.0)
                               - ((ki == 2 || kj == 2) ? 1.0 : 0.0);
            double Svi = Vr[i] - (kj == 0 ? e0v[i] : 0.0) - (kj == 2 ? e5v[i] : 0.0);
            double Svj = Vr[j] - (ki == 0 ? e0v[j] : 0.0) - (ki == 2 ? e5v[j] : 0.0);
            double Mp = a[i / 3] * a[j / 3] * Mr
                      + a[i / 3] * bo[j / 3] * Svi
                      + a[j / 3] * bo[i / 3] * Svj
                      + bo[i / 3] * bo[j / 3] * Bf * nij;
            sq += ((i == j) ? 1.0 : 2.0) * w[i] * w[j] * Mp;
        }
    }

    double mean = sy / N;
    double var  = sq / N - mean * mean;
    double sc   = (double)gg[c] / sqrt(var + 1e-5);
    g_s1[c] = (float)sc;
    g_t1[c] = (float)((double)bb[c] - mean * sc);
}

// ======================= K5: build A (fp16, half2 stores) =====================
__global__ void k_build(const float* __restrict__ cw, const float* __restrict__ cb)
{
    __shared__ float xn[3][514];
    __shared__ float4 w4[150];
    __shared__ float2 p2[C_];
    int b = blockIdx.x, t = threadIdx.x;

    for (int i = t; i < 600; i += 256) {
        int c = i / 12, j = i % 12;
        ((float*)w4)[i] = (j < 9) ? cw[c * 9 + j] : 0.f;
    }
    if (t < C_) {
        float s1 = g_s1[t], t1 = g_t1[t];
        p2[t] = make_float2(s1, cb[t] * s1 + t1);
    }
    for (int i = t; i < 3 * H_; i += 256) {
        int ch = i >> 9, h = i & 511;
        xn[ch][h + 1] = g_xs[((size_t)b * 3 + ch) * H_ + h] * g_s0[ch] + g_t0[ch];
    }
    if (t < 3) { xn[t][0] = 0.f; xn[t][513] = 0.f; }
    __syncthreads();

    float v[3][4];
    #pragma unroll
    for (int i = 0; i < 3; i++)
        #pragma unroll
        for (int k = 0; k < 4; k++)
            v[i][k] = xn[i][2 * t + k];

    __half2* arow = (__half2*)(g_a16 + (size_t)b * KIN_);
    for (int c = 0; c < C_; c++) {
        float4 wa = w4[c * 3 + 0];
        float4 wb = w4[c * 3 + 1];
        float4 wc = w4[c * 3 + 2];
        float2 ab = p2[c];
        float y0 = wa.x * v[0][0] + wa.y * v[0][1] + wa.z * v[0][2]
                 + wa.w * v[1][0] + wb.x * v[1][1] + wb.y * v[1][2]
                 + wb.z * v[2][0] + wb.w * v[2][1] + wc.x * v[2][2];
        float y1 = wa.x * v[0][1] + wa.y * v[0][2] + wa.z * v[0][3]
                 + wa.w * v[1][1] + wb.x * v[1][2] + wb.y * v[1][3]
                 + wb.z * v[2][1] + wb.w * v[2][2] + wc.x * v[2][3];
        float r0 = fmaxf(fmaf(y0, ab.x, ab.y), 0.f);
        float r1 = fmaxf(fmaf(y1, ab.x, ab.y), 0.f);
        arow[c * 256 + t] = __floats2half2_rn(r0, r1);
    }
}

// ======================= split: fp32 -> fp16 ==================================
__global__ void k_cvt16(const float* __restrict__ src, __half* __restrict__ dst, long long n)
{
    long long i = (long long)blockIdx.x * 256 + threadIdx.x;
    if (i < n) dst[i] = __float2half_rn(src[i]);
}

// ======================= fp16 NT GEMM (mma.sync m16n8k16) ====================
// Block 128x128, K-tile 64, 8 warps, 3-stage cp.async, occ 2.
// Split-K via blockIdx.z: K range [z*Klen, (z+1)*Klen), output offset z*splitStride.
constexpr int RB   = 144;
constexpr int ASZ  = 128 * RB;
constexpr int STG  = 2 * ASZ;
constexpr int NSTG = 3;
constexpr int GEMM_SMEM = NSTG * STG;        // 110592 B

__global__ __launch_bounds__(256, 2)
void k_gemm(const __half* __restrict__ A, const __half* __restrict__ Bm,
            float* __restrict__ Cm, int N, int Kd, int Klen, u64 splitStride,
            const float* __restrict__ bias, float* __restrict__ ps)
{
    extern __shared__ char smem[];
    const u32 sb = smem_u32(smem);
    const int tid  = threadIdx.x;
    const int w    = tid >> 5, lane = tid & 31;
    const int mBase = blockIdx.y * 128;
    const int nBase = blockIdx.x * 128;

    A  += (size_t)blockIdx.z * Klen;
    Bm += (size_t)blockIdx.z * Klen;
    Cm += (size_t)blockIdx.z * splitStride;

    size_t gA[4]; u32 sA[4];
    size_t gB[4]; u32 sB[4]; u32 vB[4];
    #pragma unroll
    for (int i = 0; i < 4; i++) {
        int idx = tid + i * 256;
        int r = idx >> 3, c = idx & 7;
        gA[i] = (size_t)(mBase + r) * Kd + c * 8;
        sA[i] = r * RB + c * 16;
        int n = nBase + r;
        int ok = (n < N);
        gB[i] = (size_t)(ok ? n : 0) * Kd + c * 8;
        sB[i] = r * RB + c * 16;
        vB[i] = ok ? 16u : 0u;
    }

    const int nT = Klen >> 6;

    const int wm = (w & 1) * 64;
    const int wn = (w >> 1) * 32;
    const u32 lrow = (lane & 15), lhalf = (lane >> 4) << 4;
    u32 aRel[4], bRel[2];
    #pragma unroll
    for (int i = 0; i < 4; i++) aRel[i] = (wm + i * 16 + lrow) * RB + lhalf;
    #pragma unroll
    for (int jj = 0; jj < 2; jj++) bRel[jj] = ASZ + (wn + jj * 16 + lrow) * RB + lhalf;

    float acc[4][4][4];
    #pragma unroll
    for (int i = 0; i < 4; i++)
        #pragma unroll
        for (int j = 0; j < 4; j++)
            #pragma unroll
            for (int q = 0; q < 4; q++) acc[i][j][q] = 0.f;

    #pragma unroll
    for (int p = 0; p < NSTG - 1; p++) {
        if (p < nT) {
            const u32 st = sb + p * STG;
            const size_t ko = (size_t)p * 64;
            #pragma unroll
            for (int i = 0; i < 4; i++) CP_ASYNC16(st + sA[i], A + gA[i] + ko, 16u);
            #pragma unroll
            for (int i = 0; i < 4; i++) CP_ASYNC16(st + ASZ + sB[i], Bm + gB[i] + ko, vB[i]);
        }
        CP_COMMIT();
    }

    for (int t = 0; t < nT; t++) {
        asm volatile("cp.async.wait_group 1;" ::: "memory");
        __syncthreads();

        {
            int nt = t + NSTG - 1;
            if (nt < nT) {
                const u32 st = sb + (nt % NSTG) * STG;
                const size_t ko = (size_t)nt * 64;
                #pragma unroll
                for (int i = 0; i < 4; i++) CP_ASYNC16(st + sA[i], A + gA[i] + ko, 16u);
                #pragma unroll
                for (int i = 0; i < 4; i++) CP_ASYNC16(st + ASZ + sB[i], Bm + gB[i] + ko, vB[i]);
            }
            CP_COMMIT();
        }

        const u32 stoff = sb + (t % NSTG) * STG;
        #pragma unroll
        for (int s = 0; s < 4; s++) {
            u32 ar[4][4], br[2][4];
            #pragma unroll
            for (int i = 0; i < 4; i++)
                LDM_X4(ar[i][0], ar[i][1], ar[i][2], ar[i][3], stoff + aRel[i] + s * 32);
            #pragma unroll
            for (int jj = 0; jj < 2; jj++)
                LDM_X4(br[jj][0], br[jj][1], br[jj][2], br[jj][3], stoff + bRel[jj] + s * 32);
            #pragma unroll
            for (int i = 0; i < 4; i++) {
                #pragma unroll
                for (int j = 0; j < 4; j++) {
                    MMA16816(acc[i][j], ar[i], br[j >> 1][j & 1], br[j >> 1][(j & 1) + 2]);
                }
            }
        }
    }

    // ---------------- epilogue: C stores ----------------
    const int mRow = mBase + wm + (lane >> 2);
    const int nCol = nBase + wn + ((lane & 3) << 1);
    #pragma unroll
    for (int i = 0; i < 4; i++) {
        #pragma unroll
        for (int j = 0; j < 4; j++) {
            int n = nCol + j * 8;
            if (n < N) {
                float bx = 0.f, by = 0.f;
                if (bias) { bx = bias[n]; by = bias[n + 1]; }
                int m0 = mRow + i * 16;
                float2 v0; v0.x = acc[i][j][0] + bx; v0.y = acc[i][j][1] + by;
                float2 v1; v1.x = acc[i][j][2] + bx; v1.y = acc[i][j][3] + by;
                *(float2*)(Cm + (size_t)m0 * N + n) = v0;
                *(float2*)(Cm + (size_t)(m0 + 8) * N + n) = v1;
            }
        }
    }

    // ------- fused per-row sumexp(v - SHIFT) partials (fixed shift, no max) ----
    if (ps) {
        __syncthreads();
        float* red = (float*)smem;
        const int wnIdx = w >> 1;
        #pragma unroll
        for (int i = 0; i < 4; i++) {
            #pragma unroll
            for (int h = 0; h < 2; h++) {
                float sm = 0.f;
                #pragma unroll
                for (int j = 0; j < 4; j++) {
                    int n = nCol + j * 8;
                    if (n < N) {
                        sm += __expf(acc[i][j][h * 2 + 0] - SHIFT)
                            + __expf(acc[i][j][h * 2 + 1] - SHIFT);
                    }
                }
                #pragma unroll
                for (int o = 1; o <= 2; o <<= 1)
                    sm += __shfl_xor_sync(0xffffffffu, sm, o);
                if ((lane & 3) == 0) {
                    int rloc = wm + i * 16 + h * 8 + (lane >> 2);
                    red[wnIdx * 128 + rloc] = sm;
                }
            }
        }
        __syncthreads();
        if (tid < 128) {
            float S = red[tid] + red[128 + tid] + red[256 + tid] + red[384 + tid];
            ps[(size_t)(mBase + tid) * NPAN + blockIdx.x] = S;
        }
    }
}

// ======================= K7: fused FC reduce + bias + bn2 partial stats =======
__global__ void k_fcst(const float* __restrict__ bias)
{
    int blk = blockIdx.x, t = threadIdx.x;    // 256 blocks x 256 threads
    float b0 = bias[t], b1 = bias[t + 256];
    float s0 = 0.f, q0 = 0.f, s1 = 0.f, q1 = 0.f;
    int r0 = blk * 32;
    for (int r = 0; r < 32; r++) {
        size_t o0 = (size_t)(r0 + r) * H_ + t;
        size_t o1 = o0 + 256;
        float a = b0, b = b1;
        #pragma unroll
        for (int p = 0; p < NSPL; p++) {
            a += g_fcs[(size_t)p * B_ * H_ + o0];
            b += g_fcs[(size_t)p * B_ * H_ + o1];
        }
        g_fc[o0] = a; g_fc[o1] = b;
        s0 += a; q0 += a * a;
        s1 += b; q1 += b * b;
    }
    g_part2[blk * 1024 + t]       = s0;
    g_part2[blk * 1024 + 256 + t] = q0;
    g_part2[blk * 1024 + 512 + t] = s1;
    g_part2[blk * 1024 + 768 + t] = q1;
}

// ======================= K8: finalize bn2 =====================================
__global__ void k_fin2(const float* __restrict__ gg, const float* __restrict__ bb)
{
    int n = blockIdx.x * 256 + threadIdx.x;
    int so = (n < 256) ? n : (256 + n);
    int qo = so + 256;
    double s = 0.0, q = 0.0;
    for (int j = 0; j < 256; j++) {
        s += (double)g_part2[j * 1024 + so];
        q += (double)g_part2[j * 1024 + qo];
    }
    double mean = s / (double)B_;
    double var  = q / (double)B_ - mean * mean;
    double sc   = (double)gg[n] / sqrt(var + 1e-5);
    g_s2[n] = (float)sc;
    g_t2[n] = (float)((double)bb[n] - mean * sc);
}

// ======================= K9: bn2+relu -> z fp16 ===============================
__global__ void k_bn2relu()
{
    int idx = blockIdx.x * 256 + threadIdx.x;
    int c = idx & 511;
    float v = fmaxf(fmaf(g_fc[idx], g_s2[c], g_t2[c]), 0.f);
    g_z16[idx] = __float2half_rn(v);
}

// ======================= K10: fold panel sums -> lse (chunk) ==================
__global__ void k_lse(int row0, int rows)
{
    int r = blockIdx.x * 128 + threadIdx.x;
    if (r < rows) {
        const float* psr = g_ps + (size_t)(row0 + r) * NPAN;
        float S = 0.f;
        for (int p = 0; p < NPAN; p++) S += psr[p];
        g_lse[row0 + r] = SHIFT + logf(S);
    }
}

// ======================= K11: subtract lse (chunk, single pass) ===============
__global__ void k_sub(float* __restrict__ out, int row0)
{
    int i4 = blockIdx.x * 256 + threadIdx.x;      // over rows*NE_/4 float4s
    int row = row0 + i4 / (NE_ / 4);
    float lse = g_lse[row];
    float4* p = (float4*)(out + (size_t)row0 * NE_) + i4;
    float4 v = *p;
    v.x -= lse; v.y -= lse; v.z -= lse; v.w -= lse;
    *p = v;
}

// ======================= launch ===============================================
extern "C" void kernel_launch(void* const* d_in, const int* in_sizes, int n_in,
                              void* d_out, int out_size)
{
    const int*   facts = (const int*)  d_in[0];
    const float* ent   = (const float*)d_in[1];
    const float* rel   = (const float*)d_in[2];
    const float* erb   = (const float*)d_in[3];
    const float* cw    = (const float*)d_in[4];
    const float* cb    = (const float*)d_in[5];
    const float* fcw   = (const float*)d_in[6];
    const float* fcb   = (const float*)d_in[7];
    const float* b0g   = (const float*)d_in[8];
    const float* b0b   = (const float*)d_in[9];
    const float* b1g   = (const float*)d_in[10];
    const float* b1b   = (const float*)d_in[11];
    const float* b2g   = (const float*)d_in[12];
    const float* b2b   = (const float*)d_in[13];
    float* out = (float*)d_out;

    cudaFuncSetAttribute(k_gemm, cudaFuncAttributeMaxDynamicSharedMemorySize, GEMM_SMEM);

    __half *p_a16, *p_w16, *p_e16, *p_z16;
    float *p_fcs, *p_ps;
    cudaGetSymbolAddress((void**)&p_a16, g_a16);
    cudaGetSymbolAddress((void**)&p_w16, g_w16);
    cudaGetSymbolAddress((void**)&p_e16, g_e16);
    cudaGetSymbolAddress((void**)&p_z16, g_z16);
    cudaGetSymbolAddress((void**)&p_fcs, g_fcs);
    cudaGetSymbolAddress((void**)&p_ps,  g_ps);

    k_gather<<<B_, 128>>>(facts, ent, rel, erb);
    k_fin0<<<3, 256>>>(b0g, b0b);
    k_fin1a<<<66, 256>>>();
    k_fin1b<<<1, 64>>>(cw, cb, b1g, b1b);
    k_build<<<B_, 256>>>(cw, cb);

    {
        long long nW = (long long)H_ * KIN_;
        k_cvt16<<<(u32)((nW + 255) / 256), 256>>>(fcw, p_w16, nW);
        long long nE = (long long)NE_ * H_;
        k_cvt16<<<(u32)((nE + 255) / 256), 256>>>(ent, p_e16, nE);
    }

    // FC split-K: grid (n=4, m=64, split=8); each split covers K range of 3200
    k_gemm<<<dim3(H_ / 128, B_ / 128, NSPL), 256, GEMM_SMEM>>>(
        p_a16, p_w16, p_fcs, H_, KIN_, KIN_ / NSPL, (u64)B_ * H_, nullptr, nullptr);

    k_fcst<<<256, 256>>>(fcb);
    k_fin2<<<2, 256>>>(b2g, b2b);
    k_bn2relu<<<(B_ * H_) / 256, 256>>>();

    // score GEMM + softmax in L2-resident chunks: 7 x 1152 rows + 1 x 128 rows
    {
        int row0 = 0;
        for (int c = 0; c < 8; c++) {
            int mb = (c < 7) ? 9 : 1;                 // m-blocks of 128 rows
            int rows = mb * 128;
            k_gemm<<<dim3((NE_ + 127) / 128, mb, 1), 256, GEMM_SMEM>>>(
                p_z16 + (size_t)row0 * H_, p_e16, out + (size_t)row0 * NE_,
                NE_, H_, H_, 0ull, nullptr, p_ps + (size_t)row0 * NPAN);
            k_lse<<<(rows + 127) / 128, 128>>>(row0, rows);
            k_sub<<<(rows * (NE_ / 4)) / 256, 256>>>(out, row0);
            row0 += rows;
        }
    }
}

// round 16
// speedup vs baseline: 1.0662x; 1.0662x over previous
#include <cuda_runtime.h>
#include <cuda_fp16.h>
#include <math.h>

typedef unsigned int u32;
typedef unsigned long long u64;

// Problem constants
constexpr int B_    = 8192;
constexpr int NE_   = 20000;
constexpr int H_    = 512;
constexpr int C_    = 50;
constexpr int KIN_  = 25600;          // C_*H_
constexpr int NPAN  = 157;            // ceil(20000/128) score n-panels
constexpr int NSPL  = 8;              // FC split-K factor
constexpr float SHIFT = 50.f;         // fixed softmax shift (scores |v| <~ 100)

// ---------------- scratch (static device memory; no allocations) -------------
__device__ float g_xs[(size_t)B_ * 3 * H_];
__device__ float g_part0[B_ * 6];
__device__ float g_s0[3], g_t0[3];
__device__ float g_part1[(size_t)B_ * 66];     // per-block Vraw(9)+Mraw(45)+edges(12)
__device__ double g_v66[66];
__device__ float g_s1[C_], g_t1[C_];
__device__ __half g_a16[(size_t)B_ * KIN_];    // A fp16 (420 MB)
__device__ __half g_w16[(size_t)H_ * KIN_];    // fc_w fp16
__device__ __half g_e16[(size_t)NE_ * H_];     // ent fp16
__device__ __half g_z16[(size_t)B_ * H_];      // z fp16
__device__ float g_fcs[(size_t)NSPL * B_ * H_];// FC split-K partials (128 MB)
__device__ float g_fc[B_ * H_];
__device__ float g_part2[256 * 1024];
__device__ float g_s2[H_], g_t2[H_];
__device__ float g_ps[(size_t)B_ * NPAN];      // per-panel row sumexp(v-SHIFT)
__device__ float g_lse[B_];

// ---------------- PTX helpers (portable: sm_80+ instructions only) -----------
static __device__ __forceinline__ u32 smem_u32(const void* p) {
    u32 a;
    asm("{ .reg .u64 t; cvta.to.shared.u64 t, %1; cvt.u32.u64 %0, t; }" : "=r"(a) : "l"(p));
    return a;
}

#define CP_ASYNC16(saddr, gptr, srcsz) \
    asm volatile("cp.async.cg.shared.global [%0], [%1], 16, %2;" \
                 :: "r"(saddr), "l"(gptr), "r"(srcsz) : "memory")
#define CP_COMMIT() asm volatile("cp.async.commit_group;" ::: "memory")

#define LDM_X4(r0, r1, r2, r3, addr) \
    asm volatile("ldmatrix.sync.aligned.m8n8.x4.shared.b16 {%0,%1,%2,%3}, [%4];" \
                 : "=r"(r0), "=r"(r1), "=r"(r2), "=r"(r3) : "r"(addr))

#define MMA16816(d, a, b0, b1) \
    asm volatile("mma.sync.aligned.m16n8k16.row.col.f32.f16.f16.f32 " \
                 "{%0,%1,%2,%3},{%4,%5,%6,%7},{%8,%9},{%0,%1,%2,%3};" \
                 : "+f"((d)[0]), "+f"((d)[1]), "+f"((d)[2]), "+f"((d)[3]) \
                 : "r"((a)[0]), "r"((a)[1]), "r"((a)[2]), "r"((a)[3]), \
                   "r"(b0), "r"(b1))

// ======================= K1: gather + bn0 sums + raw conv moments =============
__global__ void k_gather(const int* __restrict__ facts, const float* __restrict__ ent,
                         const float* __restrict__ rel, const float* __restrict__ erb)
{
    __shared__ float xn[3][514];        // raw values, zero-padded
    __shared__ float redm[4][54];
    __shared__ float red0[4][6];
    int b = blockIdx.x, t = threadIdx.x;   // 128 threads
    int f0 = facts[b * 3 + 0];
    int f1 = facts[b * 3 + 1];
    const float* r0 = ent + (size_t)f0 * H_;
    const float* r1 = rel + (size_t)f1 * H_;
    const float* r2 = erb + (size_t)f0 * H_;
    float* xb = g_xs + (size_t)b * 3 * H_;

    float s[3] = {0.f, 0.f, 0.f}, q[3] = {0.f, 0.f, 0.f};
    for (int h = t; h < H_; h += 128) {
        float v0 = r0[h], v1 = r1[h], v2 = r2[h];
        xb[h] = v0; xb[H_ + h] = v1; xb[2 * H_ + h] = v2;
        xn[0][h + 1] = v0; xn[1][h + 1] = v1; xn[2][h + 1] = v2;
        s[0] += v0; q[0] += v0 * v0;
        s[1] += v1; q[1] += v1 * v1;
        s[2] += v2; q[2] += v2 * v2;
    }
    if (t < 3) { xn[t][0] = 0.f; xn[t][513] = 0.f; }
    __syncthreads();

    float acc[54];
    #pragma unroll
    for (int i = 0; i < 54; i++) acc[i] = 0.f;
    #pragma unroll
    for (int jj = 0; jj < 4; jj++) {
        int h = t + jj * 128;
        float u[9];
        #pragma unroll
        for (int i = 0; i < 3; i++)
            #pragma unroll
            for (int k = 0; k < 3; k++)
                u[i * 3 + k] = xn[i][h + k];
        #pragma unroll
        for (int i = 0; i < 9; i++) acc[i] += u[i];
        int idx = 9;
        #pragma unroll
        for (int i = 0; i < 9; i++)
            #pragma unroll
            for (int j = 0; j <= i; j++)
                acc[idx++] += u[i] * u[j];
    }

    #pragma unroll
    for (int i = 0; i < 3; i++) {
        #pragma unroll
        for (int o = 16; o; o >>= 1) {
            s[i] += __shfl_xor_sync(0xffffffffu, s[i], o);
            q[i] += __shfl_xor_sync(0xffffffffu, q[i], o);
        }
    }
    #pragma unroll
    for (int i = 0; i < 54; i++) {
        #pragma unroll
        for (int o = 16; o; o >>= 1)
            acc[i] += __shfl_xor_sync(0xffffffffu, acc[i], o);
    }
    int w = t >> 5, ln = t & 31;
    if (ln == 0) {
        #pragma unroll
        for (int i = 0; i < 3; i++) { red0[w][i] = s[i]; red0[w][3 + i] = q[i]; }
        #pragma unroll
        for (int i = 0; i < 54; i++) redm[w][i] = acc[i];
    }
    __syncthreads();
    if (t < 6)
        g_part0[b * 6 + t] = red0[0][t] + red0[1][t] + red0[2][t] + red0[3][t];
    if (t < 54)
        g_part1[(size_t)b * 66 + t] = redm[0][t] + redm[1][t] + redm[2][t] + redm[3][t];
    else if (t < 66) {
        int e = t - 54, c = e >> 2, p = e & 3;
        int pos = (p == 0) ? 0 : (p == 1) ? 1 : (p == 2) ? 510 : 511;
        g_part1[(size_t)b * 66 + t] = xn[c][pos + 1];
    }
}

// ======================= K2: finalize bn0 (grid=3) ============================
__global__ void k_fin0(const float* __restrict__ gg, const float* __restrict__ bb)
{
    int c = blockIdx.x, t = threadIdx.x;
    __shared__ double sd[256], sq[256];
    double s = 0.0, q = 0.0;
    for (int j = t; j < B_; j += 256) {
        s += (double)g_part0[j * 6 + c];
        q += (double)g_part0[j * 6 + 3 + c];
    }
    sd[t] = s; sq[t] = q; __syncthreads();
    for (int o = 128; o; o >>= 1) {
        if (t < o) { sd[t] += sd[t + o]; sq[t] += sq[t + o]; }
        __syncthreads();
    }
    if (t == 0) {
        double cnt  = (double)B_ * (double)H_;
        double mean = sd[0] / cnt;
        double var  = sq[0] / cnt - mean * mean;
        double sc   = (double)gg[c] / sqrt(var + 1e-5);
        g_s0[c] = (float)sc;
        g_t0[c] = (float)((double)bb[c] - mean * sc);
    }
}

// ======================= K4a: reduce 66 raw components over blocks ============
__global__ void k_fin1a()
{
    int comp = blockIdx.x, t = threadIdx.x;
    __shared__ double sd[256];
    double s = 0.0;
    for (int j = t; j < B_; j += 256) s += (double)g_part1[(size_t)j * 66 + comp];
    sd[t] = s; __syncthreads();
    for (int o = 128; o; o >>= 1) { if (t < o) sd[t] += sd[t + o]; __syncthreads(); }
    if (t == 0) g_v66[comp] = sd[0];
}

// ======================= K4b: bn1 params (one block per channel, parallel) ====
// Terms distributed over 64 threads: tid 0..44 -> pair (i,j) of M', tid 45..53
// -> V' terms. fp64 shared tree reduce, thread 0 finalizes.
__global__ void k_fin1b(const float* __restrict__ cw, const float* __restrict__ cb,
                        const float* __restrict__ gg, const float* __restrict__ bb)
{
    __shared__ double sqs[64], dots[64];
    __shared__ double a[3], bo[3];
    int c = blockIdx.x, t = threadIdx.x;

    if (t < 3) { a[t] = (double)g_s0[t]; bo[t] = (double)g_t0[t]; }
    __syncthreads();

    double sqv = 0.0, dotv = 0.0;
    if (t < 45) {
        // map t -> (i, j), j <= i
        int i = 0;
        while ((i + 1) * (i + 2) / 2 <= t) i++;
        int j = t - i * (i + 1) / 2;
        int ki = i % 3, kj = j % 3, ci = i / 3, cj = j / 3;
        double wi = (double)cw[c * 9 + i], wj = (double)cw[c * 9 + j];
        double Bf = (double)B_;
        double Mr = g_v66[9 + t];
        double nij = 512.0 - ((ki == 0 || kj == 0) ? 1.0 : 0.0)
                           - ((ki == 2 || kj == 2) ? 1.0 : 0.0);
        // edge lookups for Sv
        double e0i = (ki == 1) ? g_v66[54 + ci * 4 + 0] : (ki == 2) ? g_v66[54 + ci * 4 + 1] : 0.0;
        double e5i = (ki == 0) ? g_v66[54 + ci * 4 + 2] : (ki == 1) ? g_v66[54 + ci * 4 + 3] : 0.0;
        double e0j = (kj == 1) ? g_v66[54 + cj * 4 + 0] : (kj == 2) ? g_v66[54 + cj * 4 + 1] : 0.0;
        double e5j = (kj == 0) ? g_v66[54 + cj * 4 + 2] : (kj == 1) ? g_v66[54 + cj * 4 + 3] : 0.0;
        double Svi = g_v66[i] - (kj == 0 ? e0i : 0.0) - (kj == 2 ? e5i : 0.0);
        double Svj = g_v66[j] - (ki == 0 ? e0j : 0.0) - (ki == 2 ? e5j : 0.0);
        double Mp = a[ci] * a[cj] * Mr
                  + a[ci] * bo[cj] * Svi
                  + a[cj] * bo[ci] * Svj
                  + bo[ci] * bo[cj] * Bf * nij;
        sqv = ((i == j) ? 1.0 : 2.0) * wi * wj * Mp;
    } else if (t < 54) {
        int i = t - 45;
        int ki = i % 3;
        double ni = 512.0 - (ki == 0 ? 1.0 : 0.0) - (ki == 2 ? 1.0 : 0.0);
        double Vp = a[i / 3] * g_v66[i] + bo[i / 3] * (double)B_ * ni;
        dotv = (double)cw[c * 9 + i] * Vp;
    }
    sqs[t] = sqv; dots[t] = dotv;
    __syncthreads();
    for (int o = 32; o; o >>= 1) {
        if (t < o) { sqs[t] += sqs[t + o]; dots[t] += dots[t + o]; }
        __syncthreads();
    }
    if (t == 0) {
        double cbv = (double)cb[c];
        double N = (double)B_ * 512.0;
        double dot = dots[0];
        double sy = cbv * N + dot;
        double sq = cbv * cbv * N + 2.0 * cbv * dot + sqs[0];
        double mean = sy / N;
        double var  = sq / N - mean * mean;
        double sc   = (double)gg[c] / sqrt(var + 1e-5);
        g_s1[c] = (float)sc;
        g_t1[c] = (float)((double)bb[c] - mean * sc);
    }
}

// ======================= K5: build A (fp16, half2 stores) =====================
__global__ void k_build(const float* __restrict__ cw, const float* __restrict__ cb)
{
    __shared__ float xn[3][514];
    __shared__ float4 w4[150];
    __shared__ float2 p2[C_];
    int b = blockIdx.x, t = threadIdx.x;

    for (int i = t; i < 600; i += 256) {
        int c = i / 12, j = i % 12;
        ((float*)w4)[i] = (j < 9) ? cw[c * 9 + j] : 0.f;
    }
    if (t < C_) {
        float s1 = g_s1[t], t1 = g_t1[t];
        p2[t] = make_float2(s1, cb[t] * s1 + t1);
    }
    for (int i = t; i < 3 * H_; i += 256) {
        int ch = i >> 9, h = i & 511;
        xn[ch][h + 1] = g_xs[((size_t)b * 3 + ch) * H_ + h] * g_s0[ch] + g_t0[ch];
    }
    if (t < 3) { xn[t][0] = 0.f; xn[t][513] = 0.f; }
    __syncthreads();

    float v[3][4];
    #pragma unroll
    for (int i = 0; i < 3; i++)
        #pragma unroll
        for (int k = 0; k < 4; k++)
            v[i][k] = xn[i][2 * t + k];

    __half2* arow = (__half2*)(g_a16 + (size_t)b * KIN_);
    for (int c = 0; c < C_; c++) {
        float4 wa = w4[c * 3 + 0];
        float4 wb = w4[c * 3 + 1];
        float4 wc = w4[c * 3 + 2];
        float2 ab = p2[c];
        float y0 = wa.x * v[0][0] + wa.y * v[0][1] + wa.z * v[0][2]
                 + wa.w * v[1][0] + wb.x * v[1][1] + wb.y * v[1][2]
                 + wb.z * v[2][0] + wb.w * v[2][1] + wc.x * v[2][2];
        float y1 = wa.x * v[0][1] + wa.y * v[0][2] + wa.z * v[0][3]
                 + wa.w * v[1][1] + wb.x * v[1][2] + wb.y * v[1][3]
                 + wb.z * v[2][1] + wb.w * v[2][2] + wc.x * v[2][3];
        float r0 = fmaxf(fmaf(y0, ab.x, ab.y), 0.f);
        float r1 = fmaxf(fmaf(y1, ab.x, ab.y), 0.f);
        arow[c * 256 + t] = __floats2half2_rn(r0, r1);
    }
}

// ======================= split: fp32 -> fp16 ==================================
__global__ void k_cvt16(const float* __restrict__ src, __half* __restrict__ dst, long long n)
{
    long long i = (long long)blockIdx.x * 256 + threadIdx.x;
    if (i < n) dst[i] = __float2half_rn(src[i]);
}

// ======================= fp16 NT GEMM (mma.sync m16n8k16) ====================
// Block 128x128, K-tile 64, 8 warps, 3-stage cp.async, occ 2.
// Split-K via blockIdx.z: K range [z*Klen, (z+1)*Klen), output offset z*splitStride.
constexpr int RB   = 144;
constexpr int ASZ  = 128 * RB;
constexpr int STG  = 2 * ASZ;
constexpr int NSTG = 3;
constexpr int GEMM_SMEM = NSTG * STG;        // 110592 B

__global__ __launch_bounds__(256, 2)
void k_gemm(const __half* __restrict__ A, const __half* __restrict__ Bm,
            float* __restrict__ Cm, int N, int Kd, int Klen, u64 splitStride,
            const float* __restrict__ bias, float* __restrict__ ps)
{
    extern __shared__ char smem[];
    const u32 sb = smem_u32(smem);
    const int tid  = threadIdx.x;
    const int w    = tid >> 5, lane = tid & 31;
    const int mBase = blockIdx.y * 128;
    const int nBase = blockIdx.x * 128;

    A  += (size_t)blockIdx.z * Klen;
    Bm += (size_t)blockIdx.z * Klen;
    Cm += (size_t)blockIdx.z * splitStride;

    size_t gA[4]; u32 sA[4];
    size_t gB[4]; u32 sB[4]; u32 vB[4];
    #pragma unroll
    for (int i = 0; i < 4; i++) {
        int idx = tid + i * 256;
        int r = idx >> 3, c = idx & 7;
        gA[i] = (size_t)(mBase + r) * Kd + c * 8;
        sA[i] = r * RB + c * 16;
        int n = nBase + r;
        int ok = (n < N);
        gB[i] = (size_t)(ok ? n : 0) * Kd + c * 8;
        sB[i] = r * RB + c * 16;
        vB[i] = ok ? 16u : 0u;
    }

    const int nT = Klen >> 6;

    const int wm = (w & 1) * 64;
    const int wn = (w >> 1) * 32;
    const u32 lrow = (lane & 15), lhalf = (lane >> 4) << 4;
    u32 aRel[4], bRel[2];
    #pragma unroll
    for (int i = 0; i < 4; i++) aRel[i] = (wm + i * 16 + lrow) * RB + lhalf;
    #pragma unroll
    for (int jj = 0; jj < 2; jj++) bRel[jj] = ASZ + (wn + jj * 16 + lrow) * RB + lhalf;

    float acc[4][4][4];
    #pragma unroll
    for (int i = 0; i < 4; i++)
        #pragma unroll
        for (int j = 0; j < 4; j++)
            #pragma unroll
            for (int q = 0; q < 4; q++) acc[i][j][q] = 0.f;

    #pragma unroll
    for (int p = 0; p < NSTG - 1; p++) {
        if (p < nT) {
            const u32 st = sb + p * STG;
            const size_t ko = (size_t)p * 64;
            #pragma unroll
            for (int i = 0; i < 4; i++) CP_ASYNC16(st + sA[i], A + gA[i] + ko, 16u);
            #pragma unroll
            for (int i = 0; i < 4; i++) CP_ASYNC16(st + ASZ + sB[i], Bm + gB[i] + ko, vB[i]);
        }
        CP_COMMIT();
    }

    for (int t = 0; t < nT; t++) {
        asm volatile("cp.async.wait_group 1;" ::: "memory");
        __syncthreads();

        {
            int nt = t + NSTG - 1;
            if (nt < nT) {
                const u32 st = sb + (nt % NSTG) * STG;
                const size_t ko = (size_t)nt * 64;
                #pragma unroll
                for (int i = 0; i < 4; i++) CP_ASYNC16(st + sA[i], A + gA[i] + ko, 16u);
                #pragma unroll
                for (int i = 0; i < 4; i++) CP_ASYNC16(st + ASZ + sB[i], Bm + gB[i] + ko, vB[i]);
            }
            CP_COMMIT();
        }

        const u32 stoff = sb + (t % NSTG) * STG;
        #pragma unroll
        for (int s = 0; s < 4; s++) {
            u32 ar[4][4], br[2][4];
            #pragma unroll
            for (int i = 0; i < 4; i++)
                LDM_X4(ar[i][0], ar[i][1], ar[i][2], ar[i][3], stoff + aRel[i] + s * 32);
            #pragma unroll
            for (int jj = 0; jj < 2; jj++)
                LDM_X4(br[jj][0], br[jj][1], br[jj][2], br[jj][3], stoff + bRel[jj] + s * 32);
            #pragma unroll
            for (int i = 0; i < 4; i++) {
                #pragma unroll
                for (int j = 0; j < 4; j++) {
                    MMA16816(acc[i][j], ar[i], br[j >> 1][j & 1], br[j >> 1][(j & 1) + 2]);
                }
            }
        }
    }

    // ---------------- epilogue: C stores ----------------
    const int mRow = mBase + wm + (lane >> 2);
    const int nCol = nBase + wn + ((lane & 3) << 1);
    #pragma unroll
    for (int i = 0; i < 4; i++) {
        #pragma unroll
        for (int j = 0; j < 4; j++) {
            int n = nCol + j * 8;
            if (n < N) {
                float bx = 0.f, by = 0.f;
                if (bias) { bx = bias[n]; by = bias[n + 1]; }
                int m0 = mRow + i * 16;
                float2 v0; v0.x = acc[i][j][0] + bx; v0.y = acc[i][j][1] + by;
                float2 v1; v1.x = acc[i][j][2] + bx; v1.y = acc[i][j][3] + by;
                *(float2*)(Cm + (size_t)m0 * N + n) = v0;
                *(float2*)(Cm + (size_t)(m0 + 8) * N + n) = v1;
            }
        }
    }

    // ------- fused per-row sumexp(v - SHIFT) partials (fixed shift, no max) ----
    if (ps) {
        __syncthreads();
        float* red = (float*)smem;
        const int wnIdx = w >> 1;
        #pragma unroll
        for (int i = 0; i < 4; i++) {
            #pragma unroll
            for (int h = 0; h < 2; h++) {
                float sm = 0.f;
                #pragma unroll
                for (int j = 0; j < 4; j++) {
                    int n = nCol + j * 8;
                    if (n < N) {
                        sm += __expf(acc[i][j][h * 2 + 0] - SHIFT)
                            + __expf(acc[i][j][h * 2 + 1] - SHIFT);
                    }
                }
                #pragma unroll
                for (int o = 1; o <= 2; o <<= 1)
                    sm += __shfl_xor_sync(0xffffffffu, sm, o);
                if ((lane & 3) == 0) {
                    int rloc = wm + i * 16 + h * 8 + (lane >> 2);
                    red[wnIdx * 128 + rloc] = sm;
                }
            }
        }
        __syncthreads();
        if (tid < 128) {
            float S = red[tid] + red[128 + tid] + red[256 + tid] + red[384 + tid];
            ps[(size_t)(mBase + tid) * NPAN + blockIdx.x] = S;
        }
    }
}

// ======================= K7: fused FC reduce + bias + bn2 partial stats =======
__global__ void k_fcst(const float* __restrict__ bias)
{
    int blk = blockIdx.x, t = threadIdx.x;    // 256 blocks x 256 threads
    float b0 = bias[t], b1 = bias[t + 256];
    float s0 = 0.f, q0 = 0.f, s1 = 0.f, q1 = 0.f;
    int r0 = blk * 32;
    for (int r = 0; r < 32; r++) {
        size_t o0 = (size_t)(r0 + r) * H_ + t;
        size_t o1 = o0 + 256;
        float a = b0, b = b1;
        #pragma unroll
        for (int p = 0; p < NSPL; p++) {
            a += g_fcs[(size_t)p * B_ * H_ + o0];
            b += g_fcs[(size_t)p * B_ * H_ + o1];
        }
        g_fc[o0] = a; g_fc[o1] = b;
        s0 += a; q0 += a * a;
        s1 += b; q1 += b * b;
    }
    g_part2[blk * 1024 + t]       = s0;
    g_part2[blk * 1024 + 256 + t] = q0;
    g_part2[blk * 1024 + 512 + t] = s1;
    g_part2[blk * 1024 + 768 + t] = q1;
}

// ======================= K8: finalize bn2 =====================================
__global__ void k_fin2(const float* __restrict__ gg, const float* __restrict__ bb)
{
    int n = blockIdx.x * 256 + threadIdx.x;
    int so = (n < 256) ? n : (256 + n);
    int qo = so + 256;
    double s = 0.0, q = 0.0;
    for (int j = 0; j < 256; j++) {
        s += (double)g_part2[j * 1024 + so];
        q += (double)g_part2[j * 1024 + qo];
    }
    double mean = s / (double)B_;
    double var  = q / (double)B_ - mean * mean;
    double sc   = (double)gg[n] / sqrt(var + 1e-5);
    g_s2[n] = (float)sc;
    g_t2[n] = (float)((double)bb[n] - mean * sc);
}

// ======================= K9: bn2+relu -> z fp16 ===============================
__global__ void k_bn2relu()
{
    int idx = blockIdx.x * 256 + threadIdx.x;
    int c = idx & 511;
    float v = fmaxf(fmaf(g_fc[idx], g_s2[c], g_t2[c]), 0.f);
    g_z16[idx] = __float2half_rn(v);
}

// ======================= K10: fold panel sums -> lse ==========================
__global__ void k_lse()
{
    int r = blockIdx.x * 256 + threadIdx.x;
    const float* psr = g_ps + (size_t)r * NPAN;
    float S = 0.f;
    for (int p = 0; p < NPAN; p++) S += psr[p];
    g_lse[r] = SHIFT + logf(S);
}

// ======================= K11: subtract lse (single pass) ======================
__global__ void k_sub(float* __restrict__ out)
{
    int i4 = blockIdx.x * 256 + threadIdx.x;
    int row = i4 / (NE_ / 4);
    float lse = g_lse[row];
    float4* p = (float4*)out + i4;
    float4 v = *p;
    v.x -= lse; v.y -= lse; v.z -= lse; v.w -= lse;
    *p = v;
}

// ======================= launch ===============================================
extern "C" void kernel_launch(void* const* d_in, const int* in_sizes, int n_in,
                              void* d_out, int out_size)
{
    const int*   facts = (const int*)  d_in[0];
    const float* ent   = (const float*)d_in[1];
    const float* rel   = (const float*)d_in[2];
    const float* erb   = (const float*)d_in[3];
    const float* cw    = (const float*)d_in[4];
    const float* cb    = (const float*)d_in[5];
    const float* fcw   = (const float*)d_in[6];
    const float* fcb   = (const float*)d_in[7];
    const float* b0g   = (const float*)d_in[8];
    const float* b0b   = (const float*)d_in[9];
    const float* b1g   = (const float*)d_in[10];
    const float* b1b   = (const float*)d_in[11];
    const float* b2g   = (const float*)d_in[12];
    const float* b2b   = (const float*)d_in[13];
    float* out = (float*)d_out;

    cudaFuncSetAttribute(k_gemm, cudaFuncAttributeMaxDynamicSharedMemorySize, GEMM_SMEM);

    __half *p_a16, *p_w16, *p_e16, *p_z16;
    float *p_fcs, *p_ps;
    cudaGetSymbolAddress((void**)&p_a16, g_a16);
    cudaGetSymbolAddress((void**)&p_w16, g_w16);
    cudaGetSymbolAddress((void**)&p_e16, g_e16);
    cudaGetSymbolAddress((void**)&p_z16, g_z16);
    cudaGetSymbolAddress((void**)&p_fcs, g_fcs);
    cudaGetSymbolAddress((void**)&p_ps,  g_ps);

    k_gather<<<B_, 128>>>(facts, ent, rel, erb);
    k_fin0<<<3, 256>>>(b0g, b0b);
    k_fin1a<<<66, 256>>>();
    k_fin1b<<<C_, 64>>>(cw, cb, b1g, b1b);
    k_build<<<B_, 256>>>(cw, cb);

    {
        long long nW = (long long)H_ * KIN_;
        k_cvt16<<<(u32)((nW + 255) / 256), 256>>>(fcw, p_w16, nW);
        long long nE = (long long)NE_ * H_;
        k_cvt16<<<(u32)((nE + 255) / 256), 256>>>(ent, p_e16, nE);
    }

    // FC split-K: grid (n=4, m=64, split=8); each split covers K range of 3200
    k_gemm<<<dim3(H_ / 128, B_ / 128, NSPL), 256, GEMM_SMEM>>>(
        p_a16, p_w16, p_fcs, H_, KIN_, KIN_ / NSPL, (u64)B_ * H_, nullptr, nullptr);

    k_fcst<<<256, 256>>>(fcb);
    k_fin2<<<2, 256>>>(b2g, b2b);
    k_bn2relu<<<(B_ * H_) / 256, 256>>>();

    // score: (8192, 512) x (20000, 512)^T -> (8192, 20000) + fused sumexp partials
    k_gemm<<<dim3((NE_ + 127) / 128, B_ / 128, 1), 256, GEMM_SMEM>>>(
        p_z16, p_e16, out, NE_, H_, H_, 0ull, nullptr, p_ps);

    k_lse<<<B_ / 256, 256>>>();
    k_sub<<<(B_ * (NE_ / 4)) / 256, 256>>>(out);
}

// round 17
// speedup vs baseline: 1.0890x; 1.0214x over previous
#include <cuda_runtime.h>
#include <cuda_fp16.h>
#include <math.h>

typedef unsigned int u32;
typedef unsigned long long u64;

// Problem constants
constexpr int B_    = 8192;
constexpr int NE_   = 20000;
constexpr int H_    = 512;
constexpr int C_    = 50;
constexpr int KIN_  = 25600;          // C_*H_
constexpr int NPAN  = 157;            // ceil(20000/128) score n-panels
constexpr int NSPL  = 8;              // FC split-K factor
constexpr float SHIFT = 50.f;         // fixed softmax shift (scores |v| <~ 100)

// ---------------- scratch (static device memory; no allocations) -------------
__device__ float g_xs[(size_t)B_ * 3 * H_];
__device__ float g_part0[B_ * 6];
__device__ float g_s0[3], g_t0[3];
__device__ float g_part1[(size_t)B_ * 66];     // per-block Vraw(9)+Mraw(45)+edges(12)
__device__ double g_v66[66];
__device__ float g_s1[C_], g_t1[C_];
__device__ __half g_a16[(size_t)B_ * KIN_];    // A fp16 (420 MB)
__device__ __half g_w16[(size_t)H_ * KIN_];    // fc_w fp16
__device__ __half g_e16[(size_t)NE_ * H_];     // ent fp16
__device__ __half g_z16[(size_t)B_ * H_];      // z fp16
__device__ float g_fcs[(size_t)NSPL * B_ * H_];// FC split-K partials (128 MB)
__device__ float g_fc[B_ * H_];
__device__ float g_part2[256 * 1024];
__device__ float g_s2[H_], g_t2[H_];
__device__ float g_ps[(size_t)B_ * NPAN];      // per-panel row sumexp(v-SHIFT)
__device__ float g_lse[B_];

// ---------------- PTX helpers (portable: sm_80+ instructions only) -----------
static __device__ __forceinline__ u32 smem_u32(const void* p) {
    u32 a;
    asm("{ .reg .u64 t; cvta.to.shared.u64 t, %1; cvt.u32.u64 %0, t; }" : "=r"(a) : "l"(p));
    return a;
}

#define CP_ASYNC16(saddr, gptr, srcsz) \
    asm volatile("cp.async.cg.shared.global [%0], [%1], 16, %2;" \
                 :: "r"(saddr), "l"(gptr), "r"(srcsz) : "memory")
#define CP_COMMIT() asm volatile("cp.async.commit_group;" ::: "memory")

#define LDM_X4(r0, r1, r2, r3, addr) \
    asm volatile("ldmatrix.sync.aligned.m8n8.x4.shared.b16 {%0,%1,%2,%3}, [%4];" \
                 : "=r"(r0), "=r"(r1), "=r"(r2), "=r"(r3) : "r"(addr))

#define MMA16816(d, a, b0, b1) \
    asm volatile("mma.sync.aligned.m16n8k16.row.col.f32.f16.f16.f32 " \
                 "{%0,%1,%2,%3},{%4,%5,%6,%7},{%8,%9},{%0,%1,%2,%3};" \
                 : "+f"((d)[0]), "+f"((d)[1]), "+f"((d)[2]), "+f"((d)[3]) \
                 : "r"((a)[0]), "r"((a)[1]), "r"((a)[2]), "r"((a)[3]), \
                   "r"(b0), "r"(b1))

// ======================= K1: gather + bn0 sums + raw conv moments =============
__global__ void k_gather(const int* __restrict__ facts, const float* __restrict__ ent,
                         const float* __restrict__ rel, const float* __restrict__ erb)
{
    __shared__ float xn[3][514];        // raw values, zero-padded
    __shared__ float redm[4][54];
    __shared__ float red0[4][6];
    int b = blockIdx.x, t = threadIdx.x;   // 128 threads
    int f0 = facts[b * 3 + 0];
    int f1 = facts[b * 3 + 1];
    const float* r0 = ent + (size_t)f0 * H_;
    const float* r1 = rel + (size_t)f1 * H_;
    const float* r2 = erb + (size_t)f0 * H_;
    float* xb = g_xs + (size_t)b * 3 * H_;

    float s[3] = {0.f, 0.f, 0.f}, q[3] = {0.f, 0.f, 0.f};
    for (int h = t; h < H_; h += 128) {
        float v0 = r0[h], v1 = r1[h], v2 = r2[h];
        xb[h] = v0; xb[H_ + h] = v1; xb[2 * H_ + h] = v2;
        xn[0][h + 1] = v0; xn[1][h + 1] = v1; xn[2][h + 1] = v2;
        s[0] += v0; q[0] += v0 * v0;
        s[1] += v1; q[1] += v1 * v1;
        s[2] += v2; q[2] += v2 * v2;
    }
    if (t < 3) { xn[t][0] = 0.f; xn[t][513] = 0.f; }
    __syncthreads();

    float acc[54];
    #pragma unroll
    for (int i = 0; i < 54; i++) acc[i] = 0.f;
    #pragma unroll
    for (int jj = 0; jj < 4; jj++) {
        int h = t + jj * 128;
        float u[9];
        #pragma unroll
        for (int i = 0; i < 3; i++)
            #pragma unroll
            for (int k = 0; k < 3; k++)
                u[i * 3 + k] = xn[i][h + k];
        #pragma unroll
        for (int i = 0; i < 9; i++) acc[i] += u[i];
        int idx = 9;
        #pragma unroll
        for (int i = 0; i < 9; i++)
            #pragma unroll
            for (int j = 0; j <= i; j++)
                acc[idx++] += u[i] * u[j];
    }

    #pragma unroll
    for (int i = 0; i < 3; i++) {
        #pragma unroll
        for (int o = 16; o; o >>= 1) {
            s[i] += __shfl_xor_sync(0xffffffffu, s[i], o);
            q[i] += __shfl_xor_sync(0xffffffffu, q[i], o);
        }
    }
    #pragma unroll
    for (int i = 0; i < 54; i++) {
        #pragma unroll
        for (int o = 16; o; o >>= 1)
            acc[i] += __shfl_xor_sync(0xffffffffu, acc[i], o);
    }
    int w = t >> 5, ln = t & 31;
    if (ln == 0) {
        #pragma unroll
        for (int i = 0; i < 3; i++) { red0[w][i] = s[i]; red0[w][3 + i] = q[i]; }
        #pragma unroll
        for (int i = 0; i < 54; i++) redm[w][i] = acc[i];
    }
    __syncthreads();
    if (t < 6)
        g_part0[b * 6 + t] = red0[0][t] + red0[1][t] + red0[2][t] + red0[3][t];
    if (t < 54)
        g_part1[(size_t)b * 66 + t] = redm[0][t] + redm[1][t] + redm[2][t] + redm[3][t];
    else if (t < 66) {
        int e = t - 54, c = e >> 2, p = e & 3;
        int pos = (p == 0) ? 0 : (p == 1) ? 1 : (p == 2) ? 510 : 511;
        g_part1[(size_t)b * 66 + t] = xn[c][pos + 1];
    }
}

// ======================= K2: finalize bn0 (grid=3) ============================
__global__ void k_fin0(const float* __restrict__ gg, const float* __restrict__ bb)
{
    int c = blockIdx.x, t = threadIdx.x;
    __shared__ double sd[256], sq[256];
    double s = 0.0, q = 0.0;
    for (int j = t; j < B_; j += 256) {
        s += (double)g_part0[j * 6 + c];
        q += (double)g_part0[j * 6 + 3 + c];
    }
    sd[t] = s; sq[t] = q; __syncthreads();
    for (int o = 128; o; o >>= 1) {
        if (t < o) { sd[t] += sd[t + o]; sq[t] += sq[t + o]; }
        __syncthreads();
    }
    if (t == 0) {
        double cnt  = (double)B_ * (double)H_;
        double mean = sd[0] / cnt;
        double var  = sq[0] / cnt - mean * mean;
        double sc   = (double)gg[c] / sqrt(var + 1e-5);
        g_s0[c] = (float)sc;
        g_t0[c] = (float)((double)bb[c] - mean * sc);
    }
}

// ======================= K4a: reduce 66 raw components over blocks ============
__global__ void k_fin1a()
{
    int comp = blockIdx.x, t = threadIdx.x;
    __shared__ double sd[256];
    double s = 0.0;
    for (int j = t; j < B_; j += 256) s += (double)g_part1[(size_t)j * 66 + comp];
    sd[t] = s; __syncthreads();
    for (int o = 128; o; o >>= 1) { if (t < o) sd[t] += sd[t + o]; __syncthreads(); }
    if (t == 0) g_v66[comp] = sd[0];
}

// ======================= K4b: bn1 params (one block per channel, parallel) ====
__global__ void k_fin1b(const float* __restrict__ cw, const float* __restrict__ cb,
                        const float* __restrict__ gg, const float* __restrict__ bb)
{
    __shared__ double sqs[64], dots[64];
    __shared__ double a[3], bo[3];
    int c = blockIdx.x, t = threadIdx.x;

    if (t < 3) { a[t] = (double)g_s0[t]; bo[t] = (double)g_t0[t]; }
    __syncthreads();

    double sqv = 0.0, dotv = 0.0;
    if (t < 45) {
        int i = 0;
        while ((i + 1) * (i + 2) / 2 <= t) i++;
        int j = t - i * (i + 1) / 2;
        int ki = i % 3, kj = j % 3, ci = i / 3, cj = j / 3;
        double wi = (double)cw[c * 9 + i], wj = (double)cw[c * 9 + j];
        double Bf = (double)B_;
        double Mr = g_v66[9 + t];
        double nij = 512.0 - ((ki == 0 || kj == 0) ? 1.0 : 0.0)
                           - ((ki == 2 || kj == 2) ? 1.0 : 0.0);
        double e0i = (ki == 1) ? g_v66[54 + ci * 4 + 0] : (ki == 2) ? g_v66[54 + ci * 4 + 1] : 0.0;
        double e5i = (ki == 0) ? g_v66[54 + ci * 4 + 2] : (ki == 1) ? g_v66[54 + ci * 4 + 3] : 0.0;
        double e0j = (kj == 1) ? g_v66[54 + cj * 4 + 0] : (kj == 2) ? g_v66[54 + cj * 4 + 1] : 0.0;
        double e5j = (kj == 0) ? g_v66[54 + cj * 4 + 2] : (kj == 1) ? g_v66[54 + cj * 4 + 3] : 0.0;
        double Svi = g_v66[i] - (kj == 0 ? e0i : 0.0) - (kj == 2 ? e5i : 0.0);
        double Svj = g_v66[j] - (ki == 0 ? e0j : 0.0) - (ki == 2 ? e5j : 0.0);
        double Mp = a[ci] * a[cj] * Mr
                  + a[ci] * bo[cj] * Svi
                  + a[cj] * bo[ci] * Svj
                  + bo[ci] * bo[cj] * Bf * nij;
        sqv = ((i == j) ? 1.0 : 2.0) * wi * wj * Mp;
    } else if (t < 54) {
        int i = t - 45;
        int ki = i % 3;
        double ni = 512.0 - (ki == 0 ? 1.0 : 0.0) - (ki == 2 ? 1.0 : 0.0);
        double Vp = a[i / 3] * g_v66[i] + bo[i / 3] * (double)B_ * ni;
        dotv = (double)cw[c * 9 + i] * Vp;
    }
    sqs[t] = sqv; dots[t] = dotv;
    __syncthreads();
    for (int o = 32; o; o >>= 1) {
        if (t < o) { sqs[t] += sqs[t + o]; dots[t] += dots[t + o]; }
        __syncthreads();
    }
    if (t == 0) {
        double cbv = (double)cb[c];
        double N = (double)B_ * 512.0;
        double dot = dots[0];
        double sy = cbv * N + dot;
        double sq = cbv * cbv * N + 2.0 * cbv * dot + sqs[0];
        double mean = sy / N;
        double var  = sq / N - mean * mean;
        double sc   = (double)gg[c] / sqrt(var + 1e-5);
        g_s1[c] = (float)sc;
        g_t1[c] = (float)((double)bb[c] - mean * sc);
    }
}

// ======================= K5: build A (fp16, half2 stores) =====================
__global__ void k_build(const float* __restrict__ cw, const float* __restrict__ cb)
{
    __shared__ float xn[3][514];
    __shared__ float4 w4[150];
    __shared__ float2 p2[C_];
    int b = blockIdx.x, t = threadIdx.x;

    for (int i = t; i < 600; i += 256) {
        int c = i / 12, j = i % 12;
        ((float*)w4)[i] = (j < 9) ? cw[c * 9 + j] : 0.f;
    }
    if (t < C_) {
        float s1 = g_s1[t], t1 = g_t1[t];
        p2[t] = make_float2(s1, cb[t] * s1 + t1);
    }
    for (int i = t; i < 3 * H_; i += 256) {
        int ch = i >> 9, h = i & 511;
        xn[ch][h + 1] = g_xs[((size_t)b * 3 + ch) * H_ + h] * g_s0[ch] + g_t0[ch];
    }
    if (t < 3) { xn[t][0] = 0.f; xn[t][513] = 0.f; }
    __syncthreads();

    float v[3][4];
    #pragma unroll
    for (int i = 0; i < 3; i++)
        #pragma unroll
        for (int k = 0; k < 4; k++)
            v[i][k] = xn[i][2 * t + k];

    __half2* arow = (__half2*)(g_a16 + (size_t)b * KIN_);
    for (int c = 0; c < C_; c++) {
        float4 wa = w4[c * 3 + 0];
        float4 wb = w4[c * 3 + 1];
        float4 wc = w4[c * 3 + 2];
        float2 ab = p2[c];
        float y0 = wa.x * v[0][0] + wa.y * v[0][1] + wa.z * v[0][2]
                 + wa.w * v[1][0] + wb.x * v[1][1] + wb.y * v[1][2]
                 + wb.z * v[2][0] + wb.w * v[2][1] + wc.x * v[2][2];
        float y1 = wa.x * v[0][1] + wa.y * v[0][2] + wa.z * v[0][3]
                 + wa.w * v[1][1] + wb.x * v[1][2] + wb.y * v[1][3]
                 + wb.z * v[2][1] + wb.w * v[2][2] + wc.x * v[2][3];
        float r0 = fmaxf(fmaf(y0, ab.x, ab.y), 0.f);
        float r1 = fmaxf(fmaf(y1, ab.x, ab.y), 0.f);
        arow[c * 256 + t] = __floats2half2_rn(r0, r1);
    }
}

// ======================= split: fp32 -> fp16 ==================================
__global__ void k_cvt16(const float* __restrict__ src, __half* __restrict__ dst, long long n)
{
    long long i = (long long)blockIdx.x * 256 + threadIdx.x;
    if (i < n) dst[i] = __float2half_rn(src[i]);
}

// ======================= fp16 NT GEMM (mma.sync m16n8k16) ====================
// Block 128x128, K-tile 64, 8 warps, 3-stage cp.async, occ 2.
// Split-K via blockIdx.z: K range [z*Klen, (z+1)*Klen), output offset z*splitStride.
constexpr int RB   = 144;
constexpr int ASZ  = 128 * RB;
constexpr int STG  = 2 * ASZ;
constexpr int NSTG = 3;
constexpr int GEMM_SMEM = NSTG * STG;        // 110592 B

__global__ __launch_bounds__(256, 2)
void k_gemm(const __half* __restrict__ A, const __half* __restrict__ Bm,
            float* __restrict__ Cm, int N, int Kd, int Klen, u64 splitStride,
            const float* __restrict__ bias, float* __restrict__ ps)
{
    extern __shared__ char smem[];
    const u32 sb = smem_u32(smem);
    const int tid  = threadIdx.x;
    const int w    = tid >> 5, lane = tid & 31;
    const int mBase = blockIdx.y * 128;
    const int nBase = blockIdx.x * 128;

    A  += (size_t)blockIdx.z * Klen;
    Bm += (size_t)blockIdx.z * Klen;
    Cm += (size_t)blockIdx.z * splitStride;

    size_t gA[4]; u32 sA[4];
    size_t gB[4]; u32 sB[4]; u32 vB[4];
    #pragma unroll
    for (int i = 0; i < 4; i++) {
        int idx = tid + i * 256;
        int r = idx >> 3, c = idx & 7;
        gA[i] = (size_t)(mBase + r) * Kd + c * 8;
        sA[i] = r * RB + c * 16;
        int n = nBase + r;
        int ok = (n < N);
        gB[i] = (size_t)(ok ? n : 0) * Kd + c * 8;
        sB[i] = r * RB + c * 16;
        vB[i] = ok ? 16u : 0u;
    }

    const int nT = Klen >> 6;

    const int wm = (w & 1) * 64;
    const int wn = (w >> 1) * 32;
    const u32 lrow = (lane & 15), lhalf = (lane >> 4) << 4;
    u32 aRel[4], bRel[2];
    #pragma unroll
    for (int i = 0; i < 4; i++) aRel[i] = (wm + i * 16 + lrow) * RB + lhalf;
    #pragma unroll
    for (int jj = 0; jj < 2; jj++) bRel[jj] = ASZ + (wn + jj * 16 + lrow) * RB + lhalf;

    float acc[4][4][4];
    #pragma unroll
    for (int i = 0; i < 4; i++)
        #pragma unroll
        for (int j = 0; j < 4; j++)
            #pragma unroll
            for (int q = 0; q < 4; q++) acc[i][j][q] = 0.f;

    #pragma unroll
    for (int p = 0; p < NSTG - 1; p++) {
        if (p < nT) {
            const u32 st = sb + p * STG;
            const size_t ko = (size_t)p * 64;
            #pragma unroll
            for (int i = 0; i < 4; i++) CP_ASYNC16(st + sA[i], A + gA[i] + ko, 16u);
            #pragma unroll
            for (int i = 0; i < 4; i++) CP_ASYNC16(st + ASZ + sB[i], Bm + gB[i] + ko, vB[i]);
        }
        CP_COMMIT();
    }

    for (int t = 0; t < nT; t++) {
        asm volatile("cp.async.wait_group 1;" ::: "memory");
        __syncthreads();

        {
            int nt = t + NSTG - 1;
            if (nt < nT) {
                const u32 st = sb + (nt % NSTG) * STG;
                const size_t ko = (size_t)nt * 64;
                #pragma unroll
                for (int i = 0; i < 4; i++) CP_ASYNC16(st + sA[i], A + gA[i] + ko, 16u);
                #pragma unroll
                for (int i = 0; i < 4; i++) CP_ASYNC16(st + ASZ + sB[i], Bm + gB[i] + ko, vB[i]);
            }
            CP_COMMIT();
        }

        const u32 stoff = sb + (t % NSTG) * STG;
        #pragma unroll
        for (int s = 0; s < 4; s++) {
            u32 ar[4][4], br[2][4];
            #pragma unroll
            for (int i = 0; i < 4; i++)
                LDM_X4(ar[i][0], ar[i][1], ar[i][2], ar[i][3], stoff + aRel[i] + s * 32);
            #pragma unroll
            for (int jj = 0; jj < 2; jj++)
                LDM_X4(br[jj][0], br[jj][1], br[jj][2], br[jj][3], stoff + bRel[jj] + s * 32);
            #pragma unroll
            for (int i = 0; i < 4; i++) {
                #pragma unroll
                for (int j = 0; j < 4; j++) {
                    MMA16816(acc[i][j], ar[i], br[j >> 1][j & 1], br[j >> 1][(j & 1) + 2]);
                }
            }
        }
    }

    // ---------------- epilogue: C stores ----------------
    const int mRow = mBase + wm + (lane >> 2);
    const int nCol = nBase + wn + ((lane & 3) << 1);
    #pragma unroll
    for (int i = 0; i < 4; i++) {
        #pragma unroll
        for (int j = 0; j < 4; j++) {
            int n = nCol + j * 8;
            if (n < N) {
                float bx = 0.f, by = 0.f;
                if (bias) { bx = bias[n]; by = bias[n + 1]; }
                int m0 = mRow + i * 16;
                float2 v0; v0.x = acc[i][j][0] + bx; v0.y = acc[i][j][1] + by;
                float2 v1; v1.x = acc[i][j][2] + bx; v1.y = acc[i][j][3] + by;
                *(float2*)(Cm + (size_t)m0 * N + n) = v0;
                *(float2*)(Cm + (size_t)(m0 + 8) * N + n) = v1;
            }
        }
    }

    // ------- fused per-row sumexp(v - SHIFT) partials (fixed shift, no max) ----
    if (ps) {
        __syncthreads();
        float* red = (float*)smem;
        const int wnIdx = w >> 1;
        #pragma unroll
        for (int i = 0; i < 4; i++) {
            #pragma unroll
            for (int h = 0; h < 2; h++) {
                float sm = 0.f;
                #pragma unroll
                for (int j = 0; j < 4; j++) {
                    int n = nCol + j * 8;
                    if (n < N) {
                        sm += __expf(acc[i][j][h * 2 + 0] - SHIFT)
                            + __expf(acc[i][j][h * 2 + 1] - SHIFT);
                    }
                }
                #pragma unroll
                for (int o = 1; o <= 2; o <<= 1)
                    sm += __shfl_xor_sync(0xffffffffu, sm, o);
                if ((lane & 3) == 0) {
                    int rloc = wm + i * 16 + h * 8 + (lane >> 2);
                    red[wnIdx * 128 + rloc] = sm;
                }
            }
        }
        __syncthreads();
        if (tid < 128) {
            float S = red[tid] + red[128 + tid] + red[256 + tid] + red[384 + tid];
            ps[(size_t)(mBase + tid) * NPAN + blockIdx.x] = S;
        }
    }
}

// ======================= K6b: reduce FC split-K partials + bias ===============
__global__ void k_fcred(const float* __restrict__ bias)
{
    int i = blockIdx.x * 256 + threadIdx.x;     // over B_*H_
    float s = bias[i & 511];
    #pragma unroll
    for (int p = 0; p < NSPL; p++) s += g_fcs[(size_t)p * B_ * H_ + i];
    g_fc[i] = s;
}

// ======================= K7: bn2 partial stats ================================
__global__ void k_stats2_part()
{
    int blk = blockIdx.x, t = threadIdx.x;
    float s0 = 0.f, q0 = 0.f, s1 = 0.f, q1 = 0.f;
    int r0 = blk * 32;
    for (int r = 0; r < 32; r++) {
        const float* row = g_fc + (size_t)(r0 + r) * H_;
        float a = row[t];
        float b = row[t + 256];
        s0 += a; q0 += a * a;
        s1 += b; q1 += b * b;
    }
    g_part2[blk * 1024 + t]       = s0;
    g_part2[blk * 1024 + 256 + t] = q0;
    g_part2[blk * 1024 + 512 + t] = s1;
    g_part2[blk * 1024 + 768 + t] = q1;
}

// ======================= K8: finalize bn2 =====================================
__global__ void k_fin2(const float* __restrict__ gg, const float* __restrict__ bb)
{
    int n = blockIdx.x * 256 + threadIdx.x;
    int so = (n < 256) ? n : (256 + n);
    int qo = so + 256;
    double s = 0.0, q = 0.0;
    for (int j = 0; j < 256; j++) {
        s += (double)g_part2[j * 1024 + so];
        q += (double)g_part2[j * 1024 + qo];
    }
    double mean = s / (double)B_;
    double var  = q / (double)B_ - mean * mean;
    double sc   = (double)gg[n] / sqrt(var + 1e-5);
    g_s2[n] = (float)sc;
    g_t2[n] = (float)((double)bb[n] - mean * sc);
}

// ======================= K9: bn2+relu -> z fp16 ===============================
__global__ void k_bn2relu()
{
    int idx = blockIdx.x * 256 + threadIdx.x;
    int c = idx & 511;
    float v = fmaxf(fmaf(g_fc[idx], g_s2[c], g_t2[c]), 0.f);
    g_z16[idx] = __float2half_rn(v);
}

// ======================= K10: fold panel sums -> lse ==========================
__global__ void k_lse()
{
    int r = blockIdx.x * 256 + threadIdx.x;
    const float* psr = g_ps + (size_t)r * NPAN;
    float S = 0.f;
    for (int p = 0; p < NPAN; p++) S += psr[p];
    g_lse[r] = SHIFT + logf(S);
}

// ======================= K11: subtract lse (single pass) ======================
__global__ void k_sub(float* __restrict__ out)
{
    int i4 = blockIdx.x * 256 + threadIdx.x;
    int row = i4 / (NE_ / 4);
    float lse = g_lse[row];
    float4* p = (float4*)out + i4;
    float4 v = *p;
    v.x -= lse; v.y -= lse; v.z -= lse; v.w -= lse;
    *p = v;
}

// ======================= launch ===============================================
extern "C" void kernel_launch(void* const* d_in, const int* in_sizes, int n_in,
                              void* d_out, int out_size)
{
    const int*   facts = (const int*)  d_in[0];
    const float* ent   = (const float*)d_in[1];
    const float* rel   = (const float*)d_in[2];
    const float* erb   = (const float*)d_in[3];
    const float* cw    = (const float*)d_in[4];
    const float* cb    = (const float*)d_in[5];
    const float* fcw   = (const float*)d_in[6];
    const float* fcb   = (const float*)d_in[7];
    const float* b0g   = (const float*)d_in[8];
    const float* b0b   = (const float*)d_in[9];
    const float* b1g   = (const float*)d_in[10];
    const float* b1b   = (const float*)d_in[11];
    const float* b2g   = (const float*)d_in[12];
    const float* b2b   = (const float*)d_in[13];
    float* out = (float*)d_out;

    cudaFuncSetAttribute(k_gemm, cudaFuncAttributeMaxDynamicSharedMemorySize, GEMM_SMEM);

    __half *p_a16, *p_w16, *p_e16, *p_z16;
    float *p_fcs, *p_ps;
    cudaGetSymbolAddress((void**)&p_a16, g_a16);
    cudaGetSymbolAddress((void**)&p_w16, g_w16);
    cudaGetSymbolAddress((void**)&p_e16, g_e16);
    cudaGetSymbolAddress((void**)&p_z16, g_z16);
    cudaGetSymbolAddress((void**)&p_fcs, g_fcs);
    cudaGetSymbolAddress((void**)&p_ps,  g_ps);

    k_gather<<<B_, 128>>>(facts, ent, rel, erb);
    k_fin0<<<3, 256>>>(b0g, b0b);
    k_fin1a<<<66, 256>>>();
    k_fin1b<<<C_, 64>>>(cw, cb, b1g, b1b);
    k_build<<<B_, 256>>>(cw, cb);

    {
        long long nW = (long long)H_ * KIN_;
        k_cvt16<<<(u32)((nW + 255) / 256), 256>>>(fcw, p_w16, nW);
        long long nE = (long long)NE_ * H_;
        k_cvt16<<<(u32)((nE + 255) / 256), 256>>>(ent, p_e16, nE);
    }

    // FC split-K: grid (n=4, m=64, split=8); each split covers K range of 3200
    k_gemm<<<dim3(H_ / 128, B_ / 128, NSPL), 256, GEMM_SMEM>>>(
        p_a16, p_w16, p_fcs, H_, KIN_, KIN_ / NSPL, (u64)B_ * H_, nullptr, nullptr);
    k_fcred<<<(B_ * H_) / 256, 256>>>(fcb);

    k_stats2_part<<<256, 256>>>();
    k_fin2<<<2, 256>>>(b2g, b2b);
    k_bn2relu<<<(B_ * H_) / 256, 256>>>();

    // score: (8192, 512) x (20000, 512)^T -> (8192, 20000) + fused sumexp partials
    k_gemm<<<dim3((NE_ + 127) / 128, B_ / 128, 1), 256, GEMM_SMEM>>>(
        p_z16, p_e16, out, NE_, H_, H_, 0ull, nullptr, p_ps);

    k_lse<<<B_ / 256, 256>>>();
    k_sub<<<(B_ * (NE_ / 4)) / 256, 256>>>(out);
}